// round 16
// baseline (speedup 1.0000x reference)
#include <cuda_runtime.h>

#define TT 11
#define THREADS 512
#define ITEMS 12
#define NW 16                            // warps per block
#define PER_BLOCK 6144
#define BMAX 8192
#define SC_FLOATS (3 * PER_BLOCK + 128)  // staging + alignment budgets

__device__ int g_blockHist[BMAX * 16];
__device__ int g_blockBase[BMAX * 16];   // includes type offset after scan
__device__ unsigned int g_ticket;        // monotonic across graph replays
__device__ unsigned int g_ptypes[BMAX * (PER_BLOCK / 4)];  // packed type bytes

__device__ __forceinline__ int fieldOf(unsigned long long q0, unsigned long long q1, int t) {
    unsigned long long q = (t < 6) ? q0 : q1;
    int sh = (t < 6) ? 10 * t : 10 * (t - 6);
    return (int)((q >> sh) & 1023ull);
}

// per-block dtype detection: read int64 words; if data is int32 the hi half of
// each word is the next type value (nonzero w.p. 10/11 per sample).
__device__ __forceinline__ int detect64(const void* types, int N, int base) {
    const long long* t64 = (const long long*)types;
    int wmax = N >> 1;
    int wi = (base >> 1) + threadIdx.x;
    if (wi >= wmax) wi = wmax - 1;
    long long v = t64[wi];
    return __syncthreads_and(v >= 0 && v < TT);
}

// 12 types -> 3 packed-byte registers
__device__ __forceinline__ void loadTypes12(const void* types, int gbase, int is64,
                                            unsigned int tp[3]) {
    if (is64) {
        const longlong2* p = (const longlong2*)((const long long*)types + gbase);
#pragma unroll
        for (int k = 0; k < 3; k++) {
            longlong2 a = p[2 * k], b = p[2 * k + 1];
            tp[k] = (unsigned)a.x | ((unsigned)a.y << 8) |
                    ((unsigned)b.x << 16) | ((unsigned)b.y << 24);
        }
    } else {
        const int4* p = (const int4*)((const int*)types + gbase);
#pragma unroll
        for (int k = 0; k < 3; k++) {
            int4 a = p[k];
            tp[k] = (unsigned)a.x | ((unsigned)a.y << 8) |
                    ((unsigned)a.z << 16) | ((unsigned)a.w << 24);
        }
    }
}

__device__ __forceinline__ int scalarType(const void* types, int i, int is64) {
    return is64 ? (int)((const long long*)types)[i] : ((const int*)types)[i];
}

// -------- pass 1: per-block histogram + packed-type publish; LAST block scans ---
__global__ void __launch_bounds__(THREADS) k_histscan(const void* __restrict__ types,
                                                      int N, int B,
                                                      float* outTail, int writeTail) {
    __shared__ unsigned long long sW0[NW], sW1[NW];
    __shared__ int sCounts[16], sOff[16], sExcl[TT * 32];
    __shared__ int sIsLast;
    int tid = threadIdx.x, lane = tid & 31, w = tid >> 5;
    int base = blockIdx.x * PER_BLOCK;
    int is64 = detect64(types, N, base);

    int myBase = base + tid * ITEMS;
    int myCnt = N - myBase; myCnt = myCnt < 0 ? 0 : (myCnt > ITEMS ? ITEMS : myCnt);
    unsigned tp[3] = {0, 0, 0};
    if (myCnt == ITEMS) {
        loadTypes12(types, myBase, is64, tp);
    } else {
        for (int j = 0; j < myCnt; j++)
            tp[j >> 2] |= (unsigned)scalarType(types, myBase + j, is64) << ((j & 3) * 8);
    }
    // publish packed bytes for the scatter pass (coalesced layout)
    {
        unsigned* pt = g_ptypes + (size_t)blockIdx.x * (PER_BLOCK / 4);
#pragma unroll
        for (int k = 0; k < 3; k++) pt[k * THREADS + tid] = tp[k];
    }

    // histogram ONLY the real items (R15 bug: counted zero padding as type 0)
    unsigned long long p0 = 0, p1 = 0;
#pragma unroll
    for (int j = 0; j < ITEMS; j++) {
        if (j < myCnt) {
            int t = (tp[j >> 2] >> ((j & 3) * 8)) & 0xFF;
            if (t < 6) p0 += 1ull << (10 * t); else p1 += 1ull << (10 * (t - 6));
        }
    }
#pragma unroll
    for (int d = 16; d; d >>= 1) {
        p0 += __shfl_xor_sync(0xffffffffu, p0, d);
        p1 += __shfl_xor_sync(0xffffffffu, p1, d);
    }
    if (lane == 0) { sW0[w] = p0; sW1[w] = p1; }
    __syncthreads();
    if (tid < TT) {
        int s = 0;
#pragma unroll
        for (int ww = 0; ww < NW; ww++) s += fieldOf(sW0[ww], sW1[ww], tid);
        g_blockHist[blockIdx.x * 16 + tid] = s;
    }
    __syncthreads();
    if (tid == 0) {
        __threadfence();
        unsigned tk = atomicAdd(&g_ticket, 1u);
        sIsLast = (((tk + 1u) % (unsigned)B) == 0u);
    }
    __syncthreads();
    if (!sIsLast) return;

    __threadfence();   // acquire
    int chunk = (B + 31) / 32;
    int s0 = lane * chunk;
    int cnt = B - s0; cnt = cnt < 0 ? 0 : (cnt > chunk ? chunk : cnt);
    for (int tt = w; tt < TT; tt += NW) {
        int sum = 0;
        for (int j = 0; j < cnt; j++) sum += g_blockHist[(s0 + j) * 16 + tt];
        int inc = sum;
#pragma unroll
        for (int d = 1; d < 32; d <<= 1) {
            int n = __shfl_up_sync(0xffffffffu, inc, d);
            if (lane >= d) inc += n;
        }
        sExcl[tt * 32 + lane] = inc - sum;
        if (lane == 31) sCounts[tt] = inc;
    }
    __syncthreads();
    if (tid == 0) {
        int run = 0;
        for (int t = 0; t < TT; t++) {
            int c = sCounts[t];
            sOff[t] = run;
            if (writeTail) { outTail[t] = (float)c; outTail[TT + t] = (float)run; }
            run += c;
        }
    }
    __syncthreads();
    for (int tt = w; tt < TT; tt += NW) {
        int run = sOff[tt] + sExcl[tt * 32 + lane];
        for (int j = 0; j < cnt; j++) {
            int v = g_blockHist[(s0 + j) * 16 + tt];
            g_blockBase[(s0 + j) * 16 + tt] = run;
            run += v;
        }
    }
}

// -------- pass 2: packed types from scratch, prefetched coords, 3 barriers ------
__global__ void __launch_bounds__(THREADS, 2) k_scatter(const float* __restrict__ coords,
                                                        float* __restrict__ out, int N) {
    extern __shared__ char smem[];
    unsigned long long* sW0 = (unsigned long long*)smem;       // @0   (8B aligned)
    unsigned long long* sW1 = sW0 + NW;                        // @128
    float* sC = (float*)(sW1 + NW);                            // @256 (16B aligned)
    int* sBase = (int*)(sC + SC_FLOATS);                       // TT*513 ints
    int* sWB = sBase + TT * 513;                               // 16*16
    int* sTot = sWB + 256;                                     // 16
    int* sLoc = sTot + 16;                                     // 16
    int* sGB3 = sLoc + 16;                                     // 16

    int tid = threadIdx.x, lane = tid & 31, w = tid >> 5;
    int blk = blockIdx.x, base = blk * PER_BLOCK;
    int nblk = min(PER_BLOCK, N - base);

    if (tid < TT) sGB3[tid] = g_blockBase[blk * 16 + tid] * 3;

    int myBase = tid * ITEMS;
    int myCnt = nblk - myBase; myCnt = myCnt < 0 ? 0 : (myCnt > ITEMS ? ITEMS : myCnt);
    bool full = (myCnt == ITEMS);

    // packed types: 3 coalesced LDG.32, no unpacking needed
    unsigned tp[3];
    {
        const unsigned* pt = g_ptypes + (size_t)blk * (PER_BLOCK / 4);
#pragma unroll
        for (int k = 0; k < 3; k++) tp[k] = pt[k * THREADS + tid];
    }
    // prefetch ALL coords up-front; the rank phases hide the DRAM latency
    float4 pf[9];
    if (full) {
        const float4* cp = (const float4*)(coords + (size_t)3 * (base + myBase));
#pragma unroll
        for (int k = 0; k < 9; k++) pf[k] = cp[k];
    } else {
        const float* cp = coords + (size_t)3 * (base + myBase);
#pragma unroll
        for (int k = 0; k < 9; k++) {
            float x = 0, y = 0, z = 0, w2 = 0;
            int o = 4 * k;
            if (o + 0 < 3 * myCnt) x = cp[o + 0];
            if (o + 1 < 3 * myCnt) y = cp[o + 1];
            if (o + 2 < 3 * myCnt) z = cp[o + 2];
            if (o + 3 < 3 * myCnt) w2 = cp[o + 3];
            pf[k] = make_float4(x, y, z, w2);
        }
    }

    // packed histogram + pre-increment nibble ranks (<=11 fits 4 bits)
    unsigned long long p0 = 0, p1 = 0, rk = 0;
#pragma unroll
    for (int j = 0; j < ITEMS; j++) {
        if (j < myCnt) {
            int t = (tp[j >> 2] >> ((j & 3) * 8)) & 0xFF;
            int sh10 = (t < 6) ? 10 * t : 10 * (t - 6);
            unsigned long long q = (t < 6) ? p0 : p1;
            rk |= ((q >> sh10) & 15ull) << (4 * j);
            if (t < 6) p0 += 1ull << sh10; else p1 += 1ull << sh10;
        }
    }
    unsigned long long m0 = p0, m1 = p1;
#pragma unroll
    for (int d = 1; d < 32; d <<= 1) {
        unsigned long long n0 = __shfl_up_sync(0xffffffffu, p0, d);
        unsigned long long n1 = __shfl_up_sync(0xffffffffu, p1, d);
        if (lane >= d) { p0 += n0; p1 += n1; }
    }
    unsigned long long e0 = p0 - m0, e1 = p1 - m1;   // exclusive within warp
    if (lane == 31) { sW0[w] = p0; sW1[w] = p1; }
    __syncthreads();                                  // ---- bar 1

    // warp 0: cross-warp bases, totals, and 4-aligned staged segment starts.
    // budget[t] = ((3*tot+3)&~3)+4 (multiple of 4) keeps each sLoc[t] congruent
    // to the global float base mod 4 after adding (gb3&3); budgets fit SC_FLOATS.
    if (tid < 32) {
        int t = lane < TT ? lane : 0;
        int run = 0;
#pragma unroll
        for (int ww = 0; ww < NW; ww++) {
            if (lane < TT) sWB[ww * 16 + lane] = run;
            run += fieldOf(sW0[ww], sW1[ww], t);
        }
        int tot = (lane < TT) ? run : 0;
        if (lane < TT) sTot[lane] = tot;
        int budget = (lane < TT) ? (((3 * tot + 3) & ~3) + 4) : 0;
        int inc = budget;
#pragma unroll
        for (int d = 1; d < 32; d <<= 1) {
            int n = __shfl_up_sync(0xffffffffu, inc, d);
            if (lane >= d) inc += n;
        }
        if (lane < TT) sLoc[lane] = (inc - budget) + (sGB3[lane] & 3);
    }
    __syncthreads();                                  // ---- bar 2

    // per-thread per-type START positions; same-thread use -> no extra barrier.
    // stride 513 ints: bank (513t+tid)%32 = (t+tid)%32 -> conflict-free per warp
#pragma unroll
    for (int t = 0; t < TT; t++)
        sBase[t * 513 + tid] = sLoc[t] + 3 * (sWB[w * 16 + t] + fieldOf(e0, e1, t));

    // replay: coords in registers, read-only same-thread table lookups
#pragma unroll
    for (int j = 0; j < ITEMS; j++) {
        if (j < myCnt) {
            int t = (tp[j >> 2] >> ((j & 3) * 8)) & 0xFF;
            int nib = (int)((rk >> (4 * j)) & 15ull);
            int r = sBase[t * 513 + tid] + 3 * nib;
            const float* f = (const float*)pf;
            sC[r + 0] = f[3 * j + 0];
            sC[r + 1] = f[3 * j + 1];
            sC[r + 2] = f[3 * j + 2];
        }
    }
    __syncthreads();                                  // ---- bar 3

    // copy-out per type: <=3 scalar head, float4 body, <=3 scalar tail
    for (int t = 0; t < TT; t++) {
        int cnt3 = sTot[t] * 3;
        if (cnt3 == 0) continue;
        int gb = sGB3[t];
        int sb = sLoc[t];
        int head = (4 - (gb & 3)) & 3;
        head = head < cnt3 ? head : cnt3;
        if (tid < head) out[(size_t)gb + tid] = sC[sb + tid];
        int rem = cnt3 - head;
        int nvec = rem >> 2;
        const float4* s4 = (const float4*)(sC + sb + head);
        float4* g4 = (float4*)(out + gb + head);
        for (int i = tid; i < nvec; i += THREADS) g4[i] = s4[i];
        int tail = rem & 3;
        int done = head + 4 * nvec;
        if (tid < tail) out[(size_t)gb + done + tid] = sC[sb + done + tid];
    }
}

extern "C" void kernel_launch(void* const* d_in, const int* in_sizes, int n_in,
                              void* d_out, int out_size) {
    const float* coords = (const float*)d_in[0];
    const void* types = d_in[1];
    int N = in_sizes[1];
    int B = (N + PER_BLOCK - 1) / PER_BLOCK;
    float* out = (float*)d_out;
    long long coordsOut = (long long)3 * N;
    int writeTail = ((long long)out_size >= coordsOut + 2 * TT) ? 1 : 0;

    const int SMEM = 98560;
    cudaFuncSetAttribute(k_scatter, cudaFuncAttributeMaxDynamicSharedMemorySize, SMEM);

    k_histscan<<<B, THREADS>>>(types, N, B, out + coordsOut, writeTail);
    k_scatter<<<B, THREADS, SMEM>>>(coords, out, N);
}